// round 14
// baseline (speedup 1.0000x reference)
#include <cuda_runtime.h>
#include <cuda_bf16.h>
#include <cstdint>

typedef unsigned long long ull;
typedef unsigned short u16;
typedef unsigned int u32;

// ---------------- Problem constants ----------------
#define A_DIM 512
#define V_DIM 768
#define L_DIM 1024
#define H_DIM 512
#define BB    16
#define SS    2048
#define ROWS  (BB * SS)        // 32768
#define G4    (4 * H_DIM)      // 2048
#define CAT_K 1536

#define CANARY 0x7FC07FC0u
#define HSTEP  (BB * H_DIM)            // 8192 words per step
#define HSEQ_WORDS ((size_t)(SS + 1) * HSTEP)

// ---------------- Scratch (device globals; no allocation allowed) ----------------
__device__ float g_cat[(size_t)ROWS * CAT_K];
__device__ float g_ctx[(size_t)ROWS * H_DIM];
__device__ float g_xg [(size_t)ROWS * G4];
__device__ float g_bsum[G4];

// per-step h stream: packed (bf_lo<<16 | bf_hi) words, canary-tagged
__device__ __align__(16) u32 g_hseq[HSEQ_WORDS];

__device__ __align__(16) u16 g_ahi[(size_t)ROWS * A_DIM],  g_alo[(size_t)ROWS * A_DIM];
__device__ __align__(16) u16 g_vhi[(size_t)ROWS * V_DIM],  g_vlo[(size_t)ROWS * V_DIM];
__device__ __align__(16) u16 g_lhi[(size_t)ROWS * L_DIM],  g_llo[(size_t)ROWS * L_DIM];
__device__ __align__(16) u16 g_cathi[(size_t)ROWS * CAT_K], g_catlo[(size_t)ROWS * CAT_K];
__device__ __align__(16) u16 g_fushi[(size_t)ROWS * H_DIM], g_fuslo[(size_t)ROWS * H_DIM];
__device__ __align__(16) u16 g_wahi[H_DIM * A_DIM],  g_walo[H_DIM * A_DIM];
__device__ __align__(16) u16 g_wvhi[H_DIM * V_DIM],  g_wvlo[H_DIM * V_DIM];
__device__ __align__(16) u16 g_wlhi[H_DIM * L_DIM],  g_wllo[H_DIM * L_DIM];
__device__ __align__(16) u16 g_wchi[H_DIM * CAT_K],  g_wclo[H_DIM * CAT_K];
__device__ __align__(16) u16 g_wihhi[G4 * H_DIM],    g_wihlo[G4 * H_DIM];

// ---------------- helpers ----------------
__device__ __forceinline__ float sigmf(float x) { return 1.0f / (1.0f + __expf(-x)); }

__device__ __forceinline__ u32 smem_u32(const void* p) {
    u32 a;
    asm("{ .reg .u64 t; cvta.to.shared.u64 t, %1; cvt.u32.u64 %0, t; }" : "=r"(a) : "l"(p));
    return a;
}

#define SWZ128(x) ((x) ^ (((x) >> 3) & 0x70))

__device__ __forceinline__ void ldsm4(u32& r0, u32& r1, u32& r2, u32& r3, u32 addr) {
    asm volatile("ldmatrix.sync.aligned.m8n8.x4.shared.b16 {%0,%1,%2,%3}, [%4];"
        : "=r"(r0), "=r"(r1), "=r"(r2), "=r"(r3) : "r"(addr));
}
__device__ __forceinline__ void mma16816(float* c, const u32* a, u32 b0, u32 b1) {
    asm volatile("mma.sync.aligned.m16n8k16.row.col.f32.bf16.bf16.f32 "
        "{%0,%1,%2,%3}, {%4,%5,%6,%7}, {%8,%9}, {%0,%1,%2,%3};"
        : "+f"(c[0]), "+f"(c[1]), "+f"(c[2]), "+f"(c[3])
        : "r"(a[0]), "r"(a[1]), "r"(a[2]), "r"(a[3]), "r"(b0), "r"(b1));
}
__device__ __forceinline__ void cp16(u32 saddr, const void* g) {
    asm volatile("cp.async.cg.shared.global [%0], [%1], 16;" :: "r"(saddr), "l"(g));
}
__device__ __forceinline__ u32 ldcg32(const u32* p) {
    u32 v; asm volatile("ld.global.cg.u32 %0, [%1];" : "=r"(v) : "l"(p)); return v;
}
__device__ __forceinline__ void stcg32(u32* p, u32 v) {
    asm volatile("st.global.cg.u32 [%0], %1;" :: "l"(p), "r"(v) : "memory");
}
__device__ __forceinline__ u16 bf_hi(float x) {
    __nv_bfloat16 h = __float2bfloat16(x); return *(u16*)&h;
}
__device__ __forceinline__ u16 bf_lo(float x) {
    __nv_bfloat16 h = __float2bfloat16(x);
    float r = x - __bfloat162float(h);
    __nv_bfloat16 l = __float2bfloat16(r);
    return *(u16*)&l;
}

// ---------------- Init: biases ----------------
__global__ void init_kernel(const float* __restrict__ bih, const float* __restrict__ bhh) {
    int i = blockIdx.x * blockDim.x + threadIdx.x;
    if (i < G4) g_bsum[i] = bih[i] + bhh[i];
}

// ---------------- hseq init: canary everywhere, slot 0 = packed h0 ----------------
__global__ void hseq_init_kernel(const float* __restrict__ h0) {
    const size_t i4 = (size_t)blockIdx.x * blockDim.x + threadIdx.x;   // uint4 index
    if (i4 >= HSEQ_WORDS / 4) return;
    if (i4 < HSTEP / 4) {
        u32 w[4];
#pragma unroll
        for (int j = 0; j < 4; j++) {
            float x = h0[i4 * 4 + j];
            w[j] = (u32)bf_hi(x) | ((u32)bf_lo(x) << 16);
        }
        ((uint4*)g_hseq)[i4] = make_uint4(w[0], w[1], w[2], w[3]);
    } else {
        ((uint4*)g_hseq)[i4] = make_uint4(CANARY, CANARY, CANARY, CANARY);
    }
}

// ---------------- fp32 -> bf16 hi/lo splits (fused, vectorized) ----------------
__device__ __forceinline__ void split4(const float* __restrict__ s, u16* __restrict__ hi,
                                       u16* __restrict__ lo, size_t i) {
    float4 x = ((const float4*)s)[i];
    float xs[4] = { x.x, x.y, x.z, x.w };
    u32 hp[2], lp[2];
#pragma unroll
    for (int q = 0; q < 2; q++) {
        u16 h0 = bf_hi(xs[2 * q]), h1 = bf_hi(xs[2 * q + 1]);
        u16 l0 = bf_lo(xs[2 * q]), l1 = bf_lo(xs[2 * q + 1]);
        hp[q] = (u32)h0 | ((u32)h1 << 16);
        lp[q] = (u32)l0 | ((u32)l1 << 16);
    }
    ((uint2*)hi)[i] = make_uint2(hp[0], hp[1]);
    ((uint2*)lo)[i] = make_uint2(lp[0], lp[1]);
}

__global__ void split_in_kernel(const float* __restrict__ a, const float* __restrict__ v,
                                const float* __restrict__ l) {
    const size_t i = (size_t)blockIdx.x * blockDim.x + threadIdx.x;
    const int seg = blockIdx.y;
    if (seg == 0) { if (i < (size_t)ROWS * A_DIM / 4) split4(a, g_ahi, g_alo, i); }
    else if (seg == 1) { if (i < (size_t)ROWS * V_DIM / 4) split4(v, g_vhi, g_vlo, i); }
    else { split4(l, g_lhi, g_llo, i); }
}

__global__ void split_w_kernel(const float* __restrict__ wa, const float* __restrict__ wv,
                               const float* __restrict__ wl, const float* __restrict__ wc,
                               const float* __restrict__ wih) {
    const size_t i = (size_t)blockIdx.x * blockDim.x + threadIdx.x;
    const int seg = blockIdx.y;
    if (seg == 0)      { if (i < (size_t)H_DIM * A_DIM / 4) split4(wa, g_wahi, g_walo, i); }
    else if (seg == 1) { if (i < (size_t)H_DIM * V_DIM / 4) split4(wv, g_wvhi, g_wvlo, i); }
    else if (seg == 2) { if (i < (size_t)H_DIM * L_DIM / 4) split4(wl, g_wlhi, g_wllo, i); }
    else if (seg == 3) { if (i < (size_t)H_DIM * CAT_K / 4) split4(wc, g_wchi, g_wclo, i); }
    else               { split4(wih, g_wihhi, g_wihlo, i); }
}

// ---------------- merged-pass pipelined mma.sync GEMM (unchanged) ----------------
#define STAGES 3
#define TILE_B 16384
#define STG_BYTES (4 * TILE_B)
#define GSMEM_BYTES (STAGES * STG_BYTES)

template<int MODE>
__global__ __launch_bounds__(256, 1)
void mma_gemm(const u16* __restrict__ Xhi, const u16* __restrict__ Xlo,
              const u16* __restrict__ Whi, const u16* __restrict__ Wlo,
              const float* __restrict__ bias, float* __restrict__ Cf,
              u16* __restrict__ Chi, u16* __restrict__ Clo,
              int K, int ldc)
{
    extern __shared__ __align__(16) char smem[];
    const u32 sbase = smem_u32(smem);

    const int tid  = threadIdx.x;
    const int lane = tid & 31;
    const int w    = tid >> 5;
    const int wm   = w & 3;
    const int wn   = w >> 2;
    const int m0 = blockIdx.y * 128;
    const int n0 = blockIdx.x * 128;

    float acc[2][8][4];
#pragma unroll
    for (int i = 0; i < 2; i++)
#pragma unroll
        for (int j = 0; j < 8; j++)
#pragma unroll
            for (int q = 0; q < 4; q++) acc[i][j][q] = 0.f;

    const int a_row = wm * 32 + (lane & 15);
    const int a_kb  = (lane >> 4) * 16;
    const int b_row = wn * 64 + (lane & 7) + ((lane >> 4) << 3);
    const int b_kb  = ((lane >> 3) & 1) * 16;

    const int KP = K / 64;

    auto issue = [&](int ch) {
        if (ch < KP) {
            const int kk = ch;
            const u16* A0 = Xhi + (size_t)m0 * K + kk * 64;
            const u16* A1 = Xlo + (size_t)m0 * K + kk * 64;
            const u16* B0 = Whi + (size_t)n0 * K + kk * 64;
            const u16* B1 = Wlo + (size_t)n0 * K + kk * 64;
            const u32 st = sbase + (ch % STAGES) * STG_BYTES;
#pragma unroll
            for (int i = 0; i < 4; i++) {
                const int id  = tid + 256 * i;
                const int row = id >> 3;
                const int c   = id & 7;
                const u32 off = SWZ128(row * 128 + c * 16);
                const size_t g = (size_t)row * K + c * 8;
                cp16(st + 0 * TILE_B + off, A0 + g);
                cp16(st + 1 * TILE_B + off, A1 + g);
                cp16(st + 2 * TILE_B + off, B0 + g);
                cp16(st + 3 * TILE_B + off, B1 + g);
            }
        }
        asm volatile("cp.async.commit_group;");
    };

    issue(0);
    issue(1);

    for (int ch = 0; ch < KP; ch++) {
        asm volatile("cp.async.wait_group 1;");
        __syncthreads();
        issue(ch + 2);

        const u32 st = sbase + (ch % STAGES) * STG_BYTES;
        const u32 sAh = st, sAl = st + TILE_B, sBh = st + 2 * TILE_B, sBl = st + 3 * TILE_B;

#pragma unroll
        for (int ks = 0; ks < 4; ks++) {
            const int kb = ks * 32;
            u32 ah[2][4], al[2][4];
#pragma unroll
            for (int mt = 0; mt < 2; mt++) {
                const u32 ao = SWZ128((a_row + mt * 16) * 128 + a_kb + kb);
                ldsm4(ah[mt][0], ah[mt][1], ah[mt][2], ah[mt][3], sAh + ao);
                ldsm4(al[mt][0], al[mt][1], al[mt][2], al[mt][3], sAl + ao);
            }
#pragma unroll
            for (int nt = 0; nt < 4; nt++) {
                const u32 bo = SWZ128((b_row + nt * 16) * 128 + b_kb + kb);
                u32 bh0, bh1, bh2, bh3, bl0, bl1, bl2, bl3;
                ldsm4(bh0, bh1, bh2, bh3, sBh + bo);
                ldsm4(bl0, bl1, bl2, bl3, sBl + bo);
#pragma unroll
                for (int mt = 0; mt < 2; mt++) {
                    mma16816(acc[mt][2 * nt],     ah[mt], bh0, bh1);
                    mma16816(acc[mt][2 * nt + 1], ah[mt], bh2, bh3);
                    mma16816(acc[mt][2 * nt],     ah[mt], bl0, bl1);
                    mma16816(acc[mt][2 * nt + 1], ah[mt], bl2, bl3);
                    mma16816(acc[mt][2 * nt],     al[mt], bh0, bh1);
                    mma16816(acc[mt][2 * nt + 1], al[mt], bh2, bh3);
                }
            }
        }
    }

    const int mb = m0 + wm * 32 + (lane >> 2);
    const int nb = n0 + wn * 64 + (lane & 3) * 2;
#pragma unroll
    for (int mt = 0; mt < 2; mt++) {
#pragma unroll
        for (int nt = 0; nt < 8; nt++) {
            const int n = nb + nt * 8;
            const float b0 = bias[n], b1 = bias[n + 1];
#pragma unroll
            for (int h = 0; h < 2; h++) {
                const int m = mb + mt * 16 + h * 8;
                float v0 = acc[mt][nt][2 * h]     + b0;
                float v1 = acc[mt][nt][2 * h + 1] + b1;
                if (MODE == 1) { v0 = tanhf(v0); v1 = tanhf(v1); }
                *(float2*)&Cf[(size_t)m * ldc + n] = make_float2(v0, v1);
                if (MODE == 0) {
                    u32 hp = (u32)bf_hi(v0) | ((u32)bf_hi(v1) << 16);
                    u32 lp = (u32)bf_lo(v0) | ((u32)bf_lo(v1) << 16);
                    *(u32*)&Chi[(size_t)m * ldc + n] = hp;
                    *(u32*)&Clo[(size_t)m * ldc + n] = lp;
                }
            }
        }
    }
}

// ---------------- Attention fusion -> bf16 hi/lo fusion ----------------
__global__ __launch_bounds__(256)
void fusion_kernel()
{
    const int warp = threadIdx.x >> 5;
    const int lane = threadIdx.x & 31;
    const int row  = blockIdx.x * 8 + warp;

    const float* crow = g_cat + (size_t)row * CAT_K;
    const float* xrow = g_ctx + (size_t)row * H_DIM;

    float av[16], vv[16], lv[16];
    float sa = 0.f, sv = 0.f, sl = 0.f;
#pragma unroll
    for (int q = 0; q < 16; q++) {
        const int k = lane + 32 * q;
        const float c = xrow[k];
        av[q] = crow[k];
        vv[q] = crow[512 + k];
        lv[q] = crow[1024 + k];
        sa = fmaf(av[q], c, sa);
        sv = fmaf(vv[q], c, sv);
        sl = fmaf(lv[q], c, sl);
    }
#pragma unroll
    for (int m = 16; m >= 1; m >>= 1) {
        sa += __shfl_xor_sync(0xffffffffu, sa, m);
        sv += __shfl_xor_sync(0xffffffffu, sv, m);
        sl += __shfl_xor_sync(0xffffffffu, sl, m);
    }
    const float mx = fmaxf(sa, fmaxf(sv, sl));
    const float ea = __expf(sa - mx);
    const float ev = __expf(sv - mx);
    const float el = __expf(sl - mx);
    const float inv = 1.0f / (ea + ev + el);
    const float wa = ea * inv, wv = ev * inv, wl = el * inv;

    u16* fh = g_fushi + (size_t)row * H_DIM;
    u16* fl = g_fuslo + (size_t)row * H_DIM;
#pragma unroll
    for (int q = 0; q < 16; q++) {
        const int k = lane + 32 * q;
        const float v = wa * av[q] + wv * vv[q] + wl * lv[q];
        fh[k] = bf_hi(v);
        fl[k] = bf_lo(v);
    }
}

// ---------------- Persistent LSTM: barrier-free dataflow (canary-tagged h stream) ----------------
#define NCTA 128
#define OFF_R ((size_t)BB * SS * H_DIM)

__global__ __launch_bounds__(256, 1)
void lstm_kernel(const float* __restrict__ c0, const float* __restrict__ Whh,
                 float* __restrict__ out)
{
    __shared__ __align__(16) float s_red[8 * 32 * 8];     // 8KB warp partials
    __shared__ float s_gates[4][4][BB];                   // 1KB
    __shared__ __align__(16) u16 s_wtile[16 * 512];       // 16KB weight staging

    const int tid  = threadIdx.x;
    const int w    = tid >> 5;
    const int lane = tid & 31;
    const int c    = blockIdx.x;

    const int b_row = (lane & 7) + ((lane >> 4) << 3);
    const int b_kb  = ((lane >> 3) & 1) * 16;
    const u32 wb = smem_u32(s_wtile);

    // one-time: stage Whh rows, capture B-fragments in registers
    u32 bfrag[2][4][4];   // [term hi/lo][ks][reg]
#pragma unroll
    for (int term = 0; term < 2; term++) {
        for (int e = tid; e < 16 * 512; e += 256) {
            const int nloc = e >> 9, k = e & 511;
            const int grow = (nloc >> 2) * H_DIM + 4 * c + (nloc & 3);
            const float wv = Whh[(size_t)grow * H_DIM + k];
            s_wtile[e] = term ? bf_lo(wv) : bf_hi(wv);
        }
        __syncthreads();
#pragma unroll
        for (int ks = 0; ks < 4; ks++) {
            const u32 addr = wb + b_row * 1024 + (64 * w + 16 * ks) * 2 + b_kb;
            ldsm4(bfrag[term][ks][0], bfrag[term][ks][1],
                  bfrag[term][ks][2], bfrag[term][ks][3], addr);
        }
        __syncthreads();
    }

    const int jn = tid >> 4;   // 0..3 (tid<64)
    const int b  = tid & 15;
    float c_val = 0.f;
    if (tid < 64) c_val = c0[b * H_DIM + 4 * c + jn];

    // per-thread A-word offsets within a step slot (8 words per ks)
    const int r0w = (lane >> 2) * 512;
    const int r1w = r0w + 8 * 512;
    const int kcw = 2 * (lane & 3) + 64 * w;

    for (int t = 0; t < SS; t++) {
        // prefetch xg (independent of recurrence)
        float xv0 = 0.f, xv1 = 0.f, xv2 = 0.f, xv3 = 0.f;
        if (tid < 64) {
            const float* xr = g_xg + ((size_t)(b * SS + t)) * G4 + 4 * c + jn;
            xv0 = xr[0 * H_DIM];
            xv1 = xr[1 * H_DIM];
            xv2 = xr[2 * H_DIM];
            xv3 = xr[3 * H_DIM];
        }

        const u32* src = g_hseq + (size_t)t * HSTEP;

        // prime all 32 word loads (MLP)
        u32 wbuf[32];
#pragma unroll
        for (int ks = 0; ks < 4; ks++) {
            const int k0 = kcw + 16 * ks;
            wbuf[ks * 8 + 0] = ldcg32(src + r0w + k0);
            wbuf[ks * 8 + 1] = ldcg32(src + r0w + k0 + 1);
            wbuf[ks * 8 + 2] = ldcg32(src + r1w + k0);
            wbuf[ks * 8 + 3] = ldcg32(src + r1w + k0 + 1);
            wbuf[ks * 8 + 4] = ldcg32(src + r0w + k0 + 8);
            wbuf[ks * 8 + 5] = ldcg32(src + r0w + k0 + 9);
            wbuf[ks * 8 + 6] = ldcg32(src + r1w + k0 + 8);
            wbuf[ks * 8 + 7] = ldcg32(src + r1w + k0 + 9);
        }
        // retry stragglers until all valid; nanosleep backoff keeps L2 spam low
        for (;;) {
            bool any = false;
#pragma unroll
            for (int ks = 0; ks < 4; ks++) {
                const int k0 = kcw + 16 * ks;
                const int od[8] = { r0w + k0, r0w + k0 + 1, r1w + k0, r1w + k0 + 1,
                                    r0w + k0 + 8, r0w + k0 + 9, r1w + k0 + 8, r1w + k0 + 9 };
#pragma unroll
                for (int i = 0; i < 8; i++)
                    if (wbuf[ks * 8 + i] == CANARY) {
                        wbuf[ks * 8 + i] = ldcg32(src + od[i]);
                        any = true;
                    }
            }
            if (!any) break;
            __nanosleep(40);
        }

        // build fragments: word = hi | lo<<16 ; ahi = hi(k)|hi(k+1)<<16
        u32 ahi[4][4], alo[4][4];
#pragma unroll
        for (int ks = 0; ks < 4; ks++)
#pragma unroll
            for (int j = 0; j < 4; j++) {
                ahi[ks][j] = __byte_perm(wbuf[ks * 8 + 2 * j], wbuf[ks * 8 + 2 * j + 1], 0x5410);
                alo[ks][j] = __byte_perm(wbuf[ks * 8 + 2 * j], wbuf[ks * 8 + 2 * j + 1], 0x7632);
            }

        float acc[2][4];
#pragma unroll
        for (int nt = 0; nt < 2; nt++)
#pragma unroll
            for (int q = 0; q < 4; q++) acc[nt][q] = 0.f;

#pragma unroll
        for (int ks = 0; ks < 4; ks++) {
#pragma unroll
            for (int nt = 0; nt < 2; nt++) {
                mma16816(acc[nt], ahi[ks], bfrag[0][ks][2 * nt], bfrag[0][ks][2 * nt + 1]);
                mma16816(acc[nt], ahi[ks], bfrag[1][ks][2 * nt], bfrag[1][ks][2 * nt + 1]);
                mma16816(acc[nt], alo[ks], bfrag[0][ks][2 * nt], bfrag[0][ks][2 * nt + 1]);
            }
        }

        // cross-warp reduction via smem (only 2 CTA barriers per step)
        *(float4*)&s_red[(w * 32 + lane) * 8]     = make_float4(acc[0][0], acc[0][1], acc[0][2], acc[0][3]);
        *(float4*)&s_red[(w * 32 + lane) * 8 + 4] = make_float4(acc[1][0], acc[1][1], acc[1][2], acc[1][3]);
        __syncthreads();
        {
            const int m = tid >> 4, nloc = tid & 15;
            const int nt = nloc >> 3;
            const int rl = ((m & 7) << 2) | ((nloc & 7) >> 1);
            const int q  = ((m >> 3) << 1) | (nloc & 1);
            float v = 0.f;
#pragma unroll
            for (int w8 = 0; w8 < 8; w8++)
                v += s_red[(w8 * 32 + rl) * 8 + nt * 4 + q];
            s_gates[nloc >> 2][nloc & 3][m] = v;
        }
        __syncthreads();

        // combine + state update + publish packed h word (self-validating)
        if (tid < 64) {
            const float gi = s_gates[0][jn][b] + xv0;
            const float gf = s_gates[1][jn][b] + xv1;
            const float gg = s_gates[2][jn][b] + xv2;
            const float go = s_gates[3][jn][b] + xv3;
            const float iv = sigmf(gi);
            const float fv = sigmf(gf);
            const float gv = tanhf(gg);
            const float ov = sigmf(go);
            c_val = fv * c_val + iv * gv;
            const float h = ov * tanhf(c_val);
            const int col = 4 * c + jn;
            const u32 word = (u32)bf_hi(h) | ((u32)bf_lo(h) << 16);
            stcg32(g_hseq + (size_t)(t + 1) * HSTEP + b * H_DIM + col, word);
            // out writes off the critical path
            out[((size_t)(b * SS + t)) * H_DIM + col] = h;
            if (t == SS - 1) {
                out[OFF_R + b * H_DIM + col]              = h;
                out[OFF_R + BB * H_DIM + b * H_DIM + col] = c_val;
            }
        }
    }
}

// ---------------- Launch ----------------
extern "C" void kernel_launch(void* const* d_in, const int* in_sizes, int n_in,
                              void* d_out, int out_size)
{
    const float* a_in = (const float*)d_in[0];
    const float* v_in = (const float*)d_in[1];
    const float* l_in = (const float*)d_in[2];
    const float* h0   = (const float*)d_in[3];
    const float* c0   = (const float*)d_in[4];
    const float* Wa   = (const float*)d_in[5];
    const float* ba   = (const float*)d_in[6];
    const float* Wv   = (const float*)d_in[7];
    const float* bv   = (const float*)d_in[8];
    const float* Wl   = (const float*)d_in[9];
    const float* bl   = (const float*)d_in[10];
    const float* Wc   = (const float*)d_in[11];
    const float* bc   = (const float*)d_in[12];
    const float* Wih  = (const float*)d_in[13];
    const float* Whh  = (const float*)d_in[14];
    const float* bih  = (const float*)d_in[15];
    const float* bhh  = (const float*)d_in[16];
    float* out = (float*)d_out;

    float *cat, *ctx, *xg, *bsum;
    cudaGetSymbolAddress((void**)&cat,  g_cat);
    cudaGetSymbolAddress((void**)&ctx,  g_ctx);
    cudaGetSymbolAddress((void**)&xg,   g_xg);
    cudaGetSymbolAddress((void**)&bsum, g_bsum);
    u16 *ahi,*alo,*vhi,*vlo,*lhi,*llo,*cathi,*catlo,*fushi,*fuslo;
    u16 *wahi,*walo,*wvhi,*wvlo,*wlhi,*wllo,*wchi,*wclo,*wihhi,*wihlo;
    cudaGetSymbolAddress((void**)&ahi, g_ahi);   cudaGetSymbolAddress((void**)&alo, g_alo);
    cudaGetSymbolAddress((void**)&vhi, g_vhi);   cudaGetSymbolAddress((void**)&vlo, g_vlo);
    cudaGetSymbolAddress((void**)&lhi, g_lhi);   cudaGetSymbolAddress((void**)&llo, g_llo);
    cudaGetSymbolAddress((void**)&cathi, g_cathi); cudaGetSymbolAddress((void**)&catlo, g_catlo);
    cudaGetSymbolAddress((void**)&fushi, g_fushi); cudaGetSymbolAddress((void**)&fuslo, g_fuslo);
    cudaGetSymbolAddress((void**)&wahi, g_wahi); cudaGetSymbolAddress((void**)&walo, g_walo);
    cudaGetSymbolAddress((void**)&wvhi, g_wvhi); cudaGetSymbolAddress((void**)&wvlo, g_wvlo);
    cudaGetSymbolAddress((void**)&wlhi, g_wlhi); cudaGetSymbolAddress((void**)&wllo, g_wllo);
    cudaGetSymbolAddress((void**)&wchi, g_wchi); cudaGetSymbolAddress((void**)&wclo, g_wclo);
    cudaGetSymbolAddress((void**)&wihhi, g_wihhi); cudaGetSymbolAddress((void**)&wihlo, g_wihlo);

    cudaFuncSetAttribute(mma_gemm<0>, cudaFuncAttributeMaxDynamicSharedMemorySize, GSMEM_BYTES);
    cudaFuncSetAttribute(mma_gemm<1>, cudaFuncAttributeMaxDynamicSharedMemorySize, GSMEM_BYTES);
    cudaFuncSetAttribute(mma_gemm<2>, cudaFuncAttributeMaxDynamicSharedMemorySize, GSMEM_BYTES);

    init_kernel<<<2, 1024>>>(bih, bhh);
    hseq_init_kernel<<<(unsigned)((HSEQ_WORDS / 4 + 255) / 256), 256>>>(h0);
    split_in_kernel<<<dim3(32768, 3), 256>>>(a_in, v_in, l_in);
    split_w_kernel<<<dim3(1024, 5), 256>>>(Wa, Wv, Wl, Wc, Wih);

    // projections -> cat fp32 + cat hi/lo (row stride 1536)
    mma_gemm<0><<<dim3(4, 256), 256, GSMEM_BYTES>>>(ahi, alo, wahi, walo, ba,
        cat,        cathi,        catlo,        A_DIM, CAT_K);
    mma_gemm<0><<<dim3(4, 256), 256, GSMEM_BYTES>>>(vhi, vlo, wvhi, wvlo, bv,
        cat + 512,  cathi + 512,  catlo + 512,  V_DIM, CAT_K);
    mma_gemm<0><<<dim3(4, 256), 256, GSMEM_BYTES>>>(lhi, llo, wlhi, wllo, bl,
        cat + 1024, cathi + 1024, catlo + 1024, L_DIM, CAT_K);

    // context = tanh(cat @ Wc^T + bc)
    mma_gemm<1><<<dim3(4, 256), 256, GSMEM_BYTES>>>(cathi, catlo, wchi, wclo, bc,
        ctx, (u16*)nullptr, (u16*)nullptr, CAT_K, H_DIM);

    // attention softmax fusion -> fus hi/lo
    fusion_kernel<<<ROWS / 8, 256>>>();

    // xg = fusion @ Wih^T + (bih + bhh)
    mma_gemm<2><<<dim3(16, 256), 256, GSMEM_BYTES>>>(fushi, fuslo, wihhi, wihlo, bsum,
        xg, (u16*)nullptr, (u16*)nullptr, H_DIM, G4);

    // recurrent LSTM (barrier-free dataflow)
    lstm_kernel<<<NCTA, 256>>>(c0, Whh, out);
}

// round 15
// speedup vs baseline: 2.4608x; 2.4608x over previous
#include <cuda_runtime.h>
#include <cuda_bf16.h>
#include <cstdint>

typedef unsigned long long ull;
typedef unsigned short u16;
typedef unsigned int u32;

// ---------------- Problem constants ----------------
#define A_DIM 512
#define V_DIM 768
#define L_DIM 1024
#define H_DIM 512
#define BB    16
#define SS    2048
#define ROWS  (BB * SS)        // 32768
#define G4    (4 * H_DIM)      // 2048
#define CAT_K 1536

// ---------------- Scratch (device globals; no allocation allowed) ----------------
__device__ float g_cat[(size_t)ROWS * CAT_K];
__device__ float g_ctx[(size_t)ROWS * H_DIM];
__device__ float g_xg [(size_t)ROWS * G4];
__device__ float g_bsum[G4];
__device__ unsigned int g_ctr;

// double-buffered recurrent h, packed (bf_hi | bf_lo<<16) u32 per element, [b][k]
__device__ __align__(16) u32 g_h2[2 * BB * H_DIM];

__device__ __align__(16) u16 g_ahi[(size_t)ROWS * A_DIM],  g_alo[(size_t)ROWS * A_DIM];
__device__ __align__(16) u16 g_vhi[(size_t)ROWS * V_DIM],  g_vlo[(size_t)ROWS * V_DIM];
__device__ __align__(16) u16 g_lhi[(size_t)ROWS * L_DIM],  g_llo[(size_t)ROWS * L_DIM];
__device__ __align__(16) u16 g_cathi[(size_t)ROWS * CAT_K], g_catlo[(size_t)ROWS * CAT_K];
__device__ __align__(16) u16 g_fushi[(size_t)ROWS * H_DIM], g_fuslo[(size_t)ROWS * H_DIM];
__device__ __align__(16) u16 g_wahi[H_DIM * A_DIM],  g_walo[H_DIM * A_DIM];
__device__ __align__(16) u16 g_wvhi[H_DIM * V_DIM],  g_wvlo[H_DIM * V_DIM];
__device__ __align__(16) u16 g_wlhi[H_DIM * L_DIM],  g_wllo[H_DIM * L_DIM];
__device__ __align__(16) u16 g_wchi[H_DIM * CAT_K],  g_wclo[H_DIM * CAT_K];
__device__ __align__(16) u16 g_wihhi[G4 * H_DIM],    g_wihlo[G4 * H_DIM];

// ---------------- helpers ----------------
__device__ __forceinline__ float sigmf(float x) { return 1.0f / (1.0f + __expf(-x)); }

__device__ __forceinline__ u32 smem_u32(const void* p) {
    u32 a;
    asm("{ .reg .u64 t; cvta.to.shared.u64 t, %1; cvt.u32.u64 %0, t; }" : "=r"(a) : "l"(p));
    return a;
}

#define SWZ128(x) ((x) ^ (((x) >> 3) & 0x70))

__device__ __forceinline__ void ldsm4(u32& r0, u32& r1, u32& r2, u32& r3, u32 addr) {
    asm volatile("ldmatrix.sync.aligned.m8n8.x4.shared.b16 {%0,%1,%2,%3}, [%4];"
        : "=r"(r0), "=r"(r1), "=r"(r2), "=r"(r3) : "r"(addr));
}
__device__ __forceinline__ void mma16816(float* c, const u32* a, u32 b0, u32 b1) {
    asm volatile("mma.sync.aligned.m16n8k16.row.col.f32.bf16.bf16.f32 "
        "{%0,%1,%2,%3}, {%4,%5,%6,%7}, {%8,%9}, {%0,%1,%2,%3};"
        : "+f"(c[0]), "+f"(c[1]), "+f"(c[2]), "+f"(c[3])
        : "r"(a[0]), "r"(a[1]), "r"(a[2]), "r"(a[3]), "r"(b0), "r"(b1));
}
__device__ __forceinline__ void cp16(u32 saddr, const void* g) {
    asm volatile("cp.async.cg.shared.global [%0], [%1], 16;" :: "r"(saddr), "l"(g));
}
__device__ __forceinline__ void ldcg64(u32& a, u32& b, const u32* p) {
    asm volatile("ld.global.cg.v2.u32 {%0,%1}, [%2];" : "=r"(a), "=r"(b) : "l"(p));
}
__device__ __forceinline__ void stcg32(u32* p, u32 v) {
    asm volatile("st.global.cg.u32 [%0], %1;" :: "l"(p), "r"(v) : "memory");
}
__device__ __forceinline__ u16 bf_hi(float x) {
    __nv_bfloat16 h = __float2bfloat16(x); return *(u16*)&h;
}
__device__ __forceinline__ u16 bf_lo(float x) {
    __nv_bfloat16 h = __float2bfloat16(x);
    float r = x - __bfloat162float(h);
    __nv_bfloat16 l = __float2bfloat16(r);
    return *(u16*)&l;
}

// ---------------- Init: biases, counter, packed h0 into slot 0 ----------------
__global__ void init_kernel(const float* __restrict__ bih, const float* __restrict__ bhh,
                            const float* __restrict__ h0) {
    int i = blockIdx.x * blockDim.x + threadIdx.x;
    if (i < G4) g_bsum[i] = bih[i] + bhh[i];
    if (i == 0) g_ctr = 0u;
    if (i < BB * H_DIM) {
        float x = h0[i];
        g_h2[i] = (u32)bf_hi(x) | ((u32)bf_lo(x) << 16);
    }
}

// ---------------- fp32 -> bf16 hi/lo splits (fused, vectorized) ----------------
__device__ __forceinline__ void split4(const float* __restrict__ s, u16* __restrict__ hi,
                                       u16* __restrict__ lo, size_t i) {
    float4 x = ((const float4*)s)[i];
    float xs[4] = { x.x, x.y, x.z, x.w };
    u32 hp[2], lp[2];
#pragma unroll
    for (int q = 0; q < 2; q++) {
        u16 h0 = bf_hi(xs[2 * q]), h1 = bf_hi(xs[2 * q + 1]);
        u16 l0 = bf_lo(xs[2 * q]), l1 = bf_lo(xs[2 * q + 1]);
        hp[q] = (u32)h0 | ((u32)h1 << 16);
        lp[q] = (u32)l0 | ((u32)l1 << 16);
    }
    ((uint2*)hi)[i] = make_uint2(hp[0], hp[1]);
    ((uint2*)lo)[i] = make_uint2(lp[0], lp[1]);
}

__global__ void split_in_kernel(const float* __restrict__ a, const float* __restrict__ v,
                                const float* __restrict__ l) {
    const size_t i = (size_t)blockIdx.x * blockDim.x + threadIdx.x;
    const int seg = blockIdx.y;
    if (seg == 0) { if (i < (size_t)ROWS * A_DIM / 4) split4(a, g_ahi, g_alo, i); }
    else if (seg == 1) { if (i < (size_t)ROWS * V_DIM / 4) split4(v, g_vhi, g_vlo, i); }
    else { split4(l, g_lhi, g_llo, i); }
}

__global__ void split_w_kernel(const float* __restrict__ wa, const float* __restrict__ wv,
                               const float* __restrict__ wl, const float* __restrict__ wc,
                               const float* __restrict__ wih) {
    const size_t i = (size_t)blockIdx.x * blockDim.x + threadIdx.x;
    const int seg = blockIdx.y;
    if (seg == 0)      { if (i < (size_t)H_DIM * A_DIM / 4) split4(wa, g_wahi, g_walo, i); }
    else if (seg == 1) { if (i < (size_t)H_DIM * V_DIM / 4) split4(wv, g_wvhi, g_wvlo, i); }
    else if (seg == 2) { if (i < (size_t)H_DIM * L_DIM / 4) split4(wl, g_wlhi, g_wllo, i); }
    else if (seg == 3) { if (i < (size_t)H_DIM * CAT_K / 4) split4(wc, g_wchi, g_wclo, i); }
    else               { split4(wih, g_wihhi, g_wihlo, i); }
}

// ---------------- merged-pass pipelined mma.sync GEMM (unchanged, proven) ----------------
#define STAGES 3
#define TILE_B 16384
#define STG_BYTES (4 * TILE_B)
#define GSMEM_BYTES (STAGES * STG_BYTES)

template<int MODE>
__global__ __launch_bounds__(256, 1)
void mma_gemm(const u16* __restrict__ Xhi, const u16* __restrict__ Xlo,
              const u16* __restrict__ Whi, const u16* __restrict__ Wlo,
              const float* __restrict__ bias, float* __restrict__ Cf,
              u16* __restrict__ Chi, u16* __restrict__ Clo,
              int K, int ldc)
{
    extern __shared__ __align__(16) char smem[];
    const u32 sbase = smem_u32(smem);

    const int tid  = threadIdx.x;
    const int lane = tid & 31;
    const int w    = tid >> 5;
    const int wm   = w & 3;
    const int wn   = w >> 2;
    const int m0 = blockIdx.y * 128;
    const int n0 = blockIdx.x * 128;

    float acc[2][8][4];
#pragma unroll
    for (int i = 0; i < 2; i++)
#pragma unroll
        for (int j = 0; j < 8; j++)
#pragma unroll
            for (int q = 0; q < 4; q++) acc[i][j][q] = 0.f;

    const int a_row = wm * 32 + (lane & 15);
    const int a_kb  = (lane >> 4) * 16;
    const int b_row = wn * 64 + (lane & 7) + ((lane >> 4) << 3);
    const int b_kb  = ((lane >> 3) & 1) * 16;

    const int KP = K / 64;

    auto issue = [&](int ch) {
        if (ch < KP) {
            const int kk = ch;
            const u16* A0 = Xhi + (size_t)m0 * K + kk * 64;
            const u16* A1 = Xlo + (size_t)m0 * K + kk * 64;
            const u16* B0 = Whi + (size_t)n0 * K + kk * 64;
            const u16* B1 = Wlo + (size_t)n0 * K + kk * 64;
            const u32 st = sbase + (ch % STAGES) * STG_BYTES;
#pragma unroll
            for (int i = 0; i < 4; i++) {
                const int id  = tid + 256 * i;
                const int row = id >> 3;
                const int c   = id & 7;
                const u32 off = SWZ128(row * 128 + c * 16);
                const size_t g = (size_t)row * K + c * 8;
                cp16(st + 0 * TILE_B + off, A0 + g);
                cp16(st + 1 * TILE_B + off, A1 + g);
                cp16(st + 2 * TILE_B + off, B0 + g);
                cp16(st + 3 * TILE_B + off, B1 + g);
            }
        }
        asm volatile("cp.async.commit_group;");
    };

    issue(0);
    issue(1);

    for (int ch = 0; ch < KP; ch++) {
        asm volatile("cp.async.wait_group 1;");
        __syncthreads();
        issue(ch + 2);

        const u32 st = sbase + (ch % STAGES) * STG_BYTES;
        const u32 sAh = st, sAl = st + TILE_B, sBh = st + 2 * TILE_B, sBl = st + 3 * TILE_B;

#pragma unroll
        for (int ks = 0; ks < 4; ks++) {
            const int kb = ks * 32;
            u32 ah[2][4], al[2][4];
#pragma unroll
            for (int mt = 0; mt < 2; mt++) {
                const u32 ao = SWZ128((a_row + mt * 16) * 128 + a_kb + kb);
                ldsm4(ah[mt][0], ah[mt][1], ah[mt][2], ah[mt][3], sAh + ao);
                ldsm4(al[mt][0], al[mt][1], al[mt][2], al[mt][3], sAl + ao);
            }
#pragma unroll
            for (int nt = 0; nt < 4; nt++) {
                const u32 bo = SWZ128((b_row + nt * 16) * 128 + b_kb + kb);
                u32 bh0, bh1, bh2, bh3, bl0, bl1, bl2, bl3;
                ldsm4(bh0, bh1, bh2, bh3, sBh + bo);
                ldsm4(bl0, bl1, bl2, bl3, sBl + bo);
#pragma unroll
                for (int mt = 0; mt < 2; mt++) {
                    mma16816(acc[mt][2 * nt],     ah[mt], bh0, bh1);
                    mma16816(acc[mt][2 * nt + 1], ah[mt], bh2, bh3);
                    mma16816(acc[mt][2 * nt],     ah[mt], bl0, bl1);
                    mma16816(acc[mt][2 * nt + 1], ah[mt], bl2, bl3);
                    mma16816(acc[mt][2 * nt],     al[mt], bh0, bh1);
                    mma16816(acc[mt][2 * nt + 1], al[mt], bh2, bh3);
                }
            }
        }
    }

    const int mb = m0 + wm * 32 + (lane >> 2);
    const int nb = n0 + wn * 64 + (lane & 3) * 2;
#pragma unroll
    for (int mt = 0; mt < 2; mt++) {
#pragma unroll
        for (int nt = 0; nt < 8; nt++) {
            const int n = nb + nt * 8;
            const float b0 = bias[n], b1 = bias[n + 1];
#pragma unroll
            for (int h = 0; h < 2; h++) {
                const int m = mb + mt * 16 + h * 8;
                float v0 = acc[mt][nt][2 * h]     + b0;
                float v1 = acc[mt][nt][2 * h + 1] + b1;
                if (MODE == 1) { v0 = tanhf(v0); v1 = tanhf(v1); }
                *(float2*)&Cf[(size_t)m * ldc + n] = make_float2(v0, v1);
                if (MODE == 0) {
                    u32 hp = (u32)bf_hi(v0) | ((u32)bf_hi(v1) << 16);
                    u32 lp = (u32)bf_lo(v0) | ((u32)bf_lo(v1) << 16);
                    *(u32*)&Chi[(size_t)m * ldc + n] = hp;
                    *(u32*)&Clo[(size_t)m * ldc + n] = lp;
                }
            }
        }
    }
}

// ---------------- Attention fusion -> bf16 hi/lo fusion ----------------
__global__ __launch_bounds__(256)
void fusion_kernel()
{
    const int warp = threadIdx.x >> 5;
    const int lane = threadIdx.x & 31;
    const int row  = blockIdx.x * 8 + warp;

    const float* crow = g_cat + (size_t)row * CAT_K;
    const float* xrow = g_ctx + (size_t)row * H_DIM;

    float av[16], vv[16], lv[16];
    float sa = 0.f, sv = 0.f, sl = 0.f;
#pragma unroll
    for (int q = 0; q < 16; q++) {
        const int k = lane + 32 * q;
        const float c = xrow[k];
        av[q] = crow[k];
        vv[q] = crow[512 + k];
        lv[q] = crow[1024 + k];
        sa = fmaf(av[q], c, sa);
        sv = fmaf(vv[q], c, sv);
        sl = fmaf(lv[q], c, sl);
    }
#pragma unroll
    for (int m = 16; m >= 1; m >>= 1) {
        sa += __shfl_xor_sync(0xffffffffu, sa, m);
        sv += __shfl_xor_sync(0xffffffffu, sv, m);
        sl += __shfl_xor_sync(0xffffffffu, sl, m);
    }
    const float mx = fmaxf(sa, fmaxf(sv, sl));
    const float ea = __expf(sa - mx);
    const float ev = __expf(sv - mx);
    const float el = __expf(sl - mx);
    const float inv = 1.0f / (ea + ev + el);
    const float wa = ea * inv, wv = ev * inv, wl = el * inv;

    u16* fh = g_fushi + (size_t)row * H_DIM;
    u16* fl = g_fuslo + (size_t)row * H_DIM;
#pragma unroll
    for (int q = 0; q < 16; q++) {
        const int k = lane + 32 * q;
        const float v = wa * av[q] + wv * vv[q] + wl * lv[q];
        fh[k] = bf_hi(v);
        fl[k] = bf_lo(v);
    }
}

// ---------------- Persistent LSTM: TC matvec, packed-h broadcast, atomic barrier ----------------
#define NCTA 128
#define OFF_R ((size_t)BB * SS * H_DIM)

__global__ __launch_bounds__(256, 1)
void lstm_kernel(const float* __restrict__ c0, const float* __restrict__ Whh,
                 float* __restrict__ out)
{
    __shared__ __align__(16) float s_red[8 * 32 * 8];     // 8KB warp partials
    __shared__ float s_gates[4][4][BB];                   // 1KB
    __shared__ __align__(16) u16 s_wtile[16 * 512];       // 16KB weight staging

    const int tid  = threadIdx.x;
    const int w    = tid >> 5;
    const int lane = tid & 31;
    const int c    = blockIdx.x;

    const int b_row = (lane & 7) + ((lane >> 4) << 3);
    const int b_kb  = ((lane >> 3) & 1) * 16;
    const u32 wb = smem_u32(s_wtile);

    // one-time: stage Whh rows, capture B-fragments in registers
    u32 bfrag[2][4][4];   // [term hi/lo][ks][reg]
#pragma unroll
    for (int term = 0; term < 2; term++) {
        for (int e = tid; e < 16 * 512; e += 256) {
            const int nloc = e >> 9, k = e & 511;
            const int grow = (nloc >> 2) * H_DIM + 4 * c + (nloc & 3);
            const float wv = Whh[(size_t)grow * H_DIM + k];
            s_wtile[e] = term ? bf_lo(wv) : bf_hi(wv);
        }
        __syncthreads();
#pragma unroll
        for (int ks = 0; ks < 4; ks++) {
            const u32 addr = wb + b_row * 1024 + (64 * w + 16 * ks) * 2 + b_kb;
            ldsm4(bfrag[term][ks][0], bfrag[term][ks][1],
                  bfrag[term][ks][2], bfrag[term][ks][3], addr);
        }
        __syncthreads();
    }

    const int jn = tid >> 4;   // 0..3 (tid<64)
    const int b  = tid & 15;
    float c_val = 0.f;
    if (tid < 64) c_val = c0[b * H_DIM + 4 * c + jn];

    // per-thread packed-h word offsets (512 words per batch)
    const int r0w = (lane >> 2) * 512;        // batch row r
    const int r1w = r0w + 8 * 512;            // batch row r+8
    const int kcw = 2 * (lane & 3) + 64 * w;  // k word base

    for (int t = 0; t < SS; t++) {
        // prefetch xg (independent of recurrence)
        float xv0 = 0.f, xv1 = 0.f, xv2 = 0.f, xv3 = 0.f;
        if (tid < 64) {
            const float* xr = g_xg + ((size_t)(b * SS + t)) * G4 + 4 * c + jn;
            xv0 = xr[0 * H_DIM];
            xv1 = xr[1 * H_DIM];
            xv2 = xr[2 * H_DIM];
            xv3 = xr[3 * H_DIM];
        }

        // wait for h_{t-1} (proven single-spinner atomic barrier)
        if (t > 0) {
            if (tid == 0) {
                const unsigned target = (unsigned)NCTA * (unsigned)t;
                while (*(volatile unsigned*)&g_ctr < target) {}
                __threadfence();
            }
            __syncthreads();
        }

        // packed-h loads from L2: 16x LDG.64 per thread
        const u32* src = g_h2 + (t & 1) * (BB * H_DIM);
        u32 wbuf[32];
#pragma unroll
        for (int ks = 0; ks < 4; ks++) {
            const int k0 = kcw + 16 * ks;
            ldcg64(wbuf[ks * 8 + 0], wbuf[ks * 8 + 1], src + r0w + k0);
            ldcg64(wbuf[ks * 8 + 2], wbuf[ks * 8 + 3], src + r1w + k0);
            ldcg64(wbuf[ks * 8 + 4], wbuf[ks * 8 + 5], src + r0w + k0 + 8);
            ldcg64(wbuf[ks * 8 + 6], wbuf[ks * 8 + 7], src + r1w + k0 + 8);
        }

        // build fragments: word = hi | lo<<16
        u32 ahi[4][4], alo[4][4];
#pragma unroll
        for (int ks = 0; ks < 4; ks++)
#pragma unroll
            for (int j = 0; j < 4; j++) {
                ahi[ks][j] = __byte_perm(wbuf[ks * 8 + 2 * j], wbuf[ks * 8 + 2 * j + 1], 0x5410);
                alo[ks][j] = __byte_perm(wbuf[ks * 8 + 2 * j], wbuf[ks * 8 + 2 * j + 1], 0x7632);
            }

        float acc[2][4];
#pragma unroll
        for (int nt = 0; nt < 2; nt++)
#pragma unroll
            for (int q = 0; q < 4; q++) acc[nt][q] = 0.f;

#pragma unroll
        for (int ks = 0; ks < 4; ks++) {
#pragma unroll
            for (int nt = 0; nt < 2; nt++) {
                mma16816(acc[nt], ahi[ks], bfrag[0][ks][2 * nt], bfrag[0][ks][2 * nt + 1]);
                mma16816(acc[nt], ahi[ks], bfrag[1][ks][2 * nt], bfrag[1][ks][2 * nt + 1]);
                mma16816(acc[nt], alo[ks], bfrag[0][ks][2 * nt], bfrag[0][ks][2 * nt + 1]);
            }
        }

        // cross-warp reduction via smem
        *(float4*)&s_red[(w * 32 + lane) * 8]     = make_float4(acc[0][0], acc[0][1], acc[0][2], acc[0][3]);
        *(float4*)&s_red[(w * 32 + lane) * 8 + 4] = make_float4(acc[1][0], acc[1][1], acc[1][2], acc[1][3]);
        __syncthreads();
        {
            const int m = tid >> 4, nloc = tid & 15;
            const int nt = nloc >> 3;
            const int rl = ((m & 7) << 2) | ((nloc & 7) >> 1);
            const int q  = ((m >> 3) << 1) | (nloc & 1);
            float v = 0.f;
#pragma unroll
            for (int w8 = 0; w8 < 8; w8++)
                v += s_red[(w8 * 32 + rl) * 8 + nt * 4 + q];
            s_gates[nloc >> 2][nloc & 3][m] = v;
        }
        __syncthreads();

        // combine + state update + publish packed h word
        float h = 0.f;
        int col = 0;
        if (tid < 64) {
            const float gi = s_gates[0][jn][b] + xv0;
            const float gf = s_gates[1][jn][b] + xv1;
            const float gg = s_gates[2][jn][b] + xv2;
            const float go = s_gates[3][jn][b] + xv3;
            const float iv = sigmf(gi);
            const float fv = sigmf(gf);
            const float gv = tanhf(gg);
            const float ov = sigmf(go);
            c_val = fv * c_val + iv * gv;
            h = ov * tanhf(c_val);
            col = 4 * c + jn;
            const u32 word = (u32)bf_hi(h) | ((u32)bf_lo(h) << 16);
            stcg32(g_h2 + ((t + 1) & 1) * (BB * H_DIM) + b * H_DIM + col, word);
        }
        __syncthreads();
        if (tid == 0) {
            __threadfence();
            atomicAdd(&g_ctr, 1u);
        }

        // out writes OFF the critical path (after signal)
        if (tid < 64) {
            out[((size_t)(b * SS + t)) * H_DIM + col] = h;
            if (t == SS - 1) {
                out[OFF_R + b * H_DIM + col]              = h;
                out[OFF_R + BB * H_DIM + b * H_DIM + col] = c_val;
            }
        }
    }
}

// ---------------- Launch ----------------
extern "C" void kernel_launch(void* const* d_in, const int* in_sizes, int n_in,
                              void* d_out, int out_size)
{
    const float* a_in = (const float*)d_in[0];
    const float* v_in = (const float*)d_in[1];
    const float* l_in = (const float*)d_in[2];
    const float* h0   = (const float*)d_in[3];
    const float* c0   = (const float*)d_in[4];
    const float* Wa   = (const float*)d_in[5];
    const float* ba   = (const float*)d_in[6];
    const float* Wv   = (const float*)d_in[7];
    const float* bv   = (const float*)d_in[8];
    const float* Wl   = (const float*)d_in[9];
    const float* bl   = (const float*)d_in[10];
    const float* Wc   = (const float*)d_in[11];
    const float* bc   = (const float*)d_in[12];
    const float* Wih  = (const float*)d_in[13];
    const float* Whh  = (const float*)d_in[14];
    const float* bih  = (const float*)d_in[15];
    const float* bhh  = (const float*)d_in[16];
    float* out = (float*)d_out;

    float *cat, *ctx, *xg, *bsum;
    cudaGetSymbolAddress((void**)&cat,  g_cat);
    cudaGetSymbolAddress((void**)&ctx,  g_ctx);
    cudaGetSymbolAddress((void**)&xg,   g_xg);
    cudaGetSymbolAddress((void**)&bsum, g_bsum);
    u16 *ahi,*alo,*vhi,*vlo,*lhi,*llo,*cathi,*catlo,*fushi,*fuslo;
    u16 *wahi,*walo,*wvhi,*wvlo,*wlhi,*wllo,*wchi,*wclo,*wihhi,*wihlo;
    cudaGetSymbolAddress((void**)&ahi, g_ahi);   cudaGetSymbolAddress((void**)&alo, g_alo);
    cudaGetSymbolAddress((void**)&vhi, g_vhi);   cudaGetSymbolAddress((void**)&vlo, g_vlo);
    cudaGetSymbolAddress((void**)&lhi, g_lhi);   cudaGetSymbolAddress((void**)&llo, g_llo);
    cudaGetSymbolAddress((void**)&cathi, g_cathi); cudaGetSymbolAddress((void**)&catlo, g_catlo);
    cudaGetSymbolAddress((void**)&fushi, g_fushi); cudaGetSymbolAddress((void**)&fuslo, g_fuslo);
    cudaGetSymbolAddress((void**)&wahi, g_wahi); cudaGetSymbolAddress((void**)&walo, g_walo);
    cudaGetSymbolAddress((void**)&wvhi, g_wvhi); cudaGetSymbolAddress((void**)&wvlo, g_wvlo);
    cudaGetSymbolAddress((void**)&wlhi, g_wlhi); cudaGetSymbolAddress((void**)&wllo, g_wllo);
    cudaGetSymbolAddress((void**)&wchi, g_wchi); cudaGetSymbolAddress((void**)&wclo, g_wclo);
    cudaGetSymbolAddress((void**)&wihhi, g_wihhi); cudaGetSymbolAddress((void**)&wihlo, g_wihlo);

    cudaFuncSetAttribute(mma_gemm<0>, cudaFuncAttributeMaxDynamicSharedMemorySize, GSMEM_BYTES);
    cudaFuncSetAttribute(mma_gemm<1>, cudaFuncAttributeMaxDynamicSharedMemorySize, GSMEM_BYTES);
    cudaFuncSetAttribute(mma_gemm<2>, cudaFuncAttributeMaxDynamicSharedMemorySize, GSMEM_BYTES);

    init_kernel<<<8, 1024>>>(bih, bhh, h0);
    split_in_kernel<<<dim3(32768, 3), 256>>>(a_in, v_in, l_in);
    split_w_kernel<<<dim3(1024, 5), 256>>>(Wa, Wv, Wl, Wc, Wih);

    // projections -> cat fp32 + cat hi/lo (row stride 1536)
    mma_gemm<0><<<dim3(4, 256), 256, GSMEM_BYTES>>>(ahi, alo, wahi, walo, ba,
        cat,        cathi,        catlo,        A_DIM, CAT_K);
    mma_gemm<0><<<dim3(4, 256), 256, GSMEM_BYTES>>>(vhi, vlo, wvhi, wvlo, bv,
        cat + 512,  cathi + 512,  catlo + 512,  V_DIM, CAT_K);
    mma_gemm<0><<<dim3(4, 256), 256, GSMEM_BYTES>>>(lhi, llo, wlhi, wllo, bl,
        cat + 1024, cathi + 1024, catlo + 1024, L_DIM, CAT_K);

    // context = tanh(cat @ Wc^T + bc)
    mma_gemm<1><<<dim3(4, 256), 256, GSMEM_BYTES>>>(cathi, catlo, wchi, wclo, bc,
        ctx, (u16*)nullptr, (u16*)nullptr, CAT_K, H_DIM);

    // attention softmax fusion -> fus hi/lo
    fusion_kernel<<<ROWS / 8, 256>>>();

    // xg = fusion @ Wih^T + (bih + bhh)
    mma_gemm<2><<<dim3(16, 256), 256, GSMEM_BYTES>>>(fushi, fuslo, wihhi, wihlo, bsum,
        xg, (u16*)nullptr, (u16*)nullptr, H_DIM, G4);

    // recurrent LSTM (tensor-core, packed-h, atomic barrier)
    lstm_kernel<<<NCTA, 256>>>(c0, Whh, out);
}